// round 12
// baseline (speedup 1.0000x reference)
#include <cuda_runtime.h>
#include <cuda_bf16.h>

// char_feats: [L=512, B=256, D=256] f32 (time-major)
// word_ids:   [B, L] i32 (per-row non-decreasing, dense 0..n-1, < 128)
// attention_mask: [B, L] i32
// out: word_feats [W=128, B, D] f32 (+ masks [W, B] f32 if out_size allows)
#define LSEQ 512
#define NW   128
#define BATCH 256
#define DDIM  256
#define WPB   8                 // words per block (one 64-thread group each)
#define NTHREADS (64 * WPB)     // 512 == LSEQ: one id/mask element per thread
#define NWARPS (NTHREADS / 32)

__device__ __forceinline__ int clampw(int v) {
    return v < 0 ? 0 : (v > NW - 1 ? NW - 1 : v);
}

// 4/2/1 ladder; single accumulator; evict-first streaming loads.
__device__ __forceinline__ float4 pool_body(const float4* p, int stride4, int n) {
    float4 acc = make_float4(0.f, 0.f, 0.f, 0.f);
    int rem = n;
    while (rem >= 4) {
        float4 v0 = __ldcs(p);
        float4 v1 = __ldcs(p + stride4);
        float4 v2 = __ldcs(p + 2 * stride4);
        float4 v3 = __ldcs(p + 3 * stride4);
        acc.x += v0.x; acc.y += v0.y; acc.z += v0.z; acc.w += v0.w;
        acc.x += v1.x; acc.y += v1.y; acc.z += v1.z; acc.w += v1.w;
        acc.x += v2.x; acc.y += v2.y; acc.z += v2.z; acc.w += v2.w;
        acc.x += v3.x; acc.y += v3.y; acc.z += v3.z; acc.w += v3.w;
        p += 4 * stride4;
        rem -= 4;
    }
    if (rem >= 2) {
        float4 v0 = __ldcs(p);
        float4 v1 = __ldcs(p + stride4);
        acc.x += v0.x; acc.y += v0.y; acc.z += v0.z; acc.w += v0.w;
        acc.x += v1.x; acc.y += v1.y; acc.z += v1.z; acc.w += v1.w;
        p += 2 * stride4;
        rem -= 2;
    }
    if (rem >= 1) {
        float4 v0 = __ldcs(p);
        acc.x += v0.x; acc.y += v0.y; acc.z += v0.z; acc.w += v0.w;
    }
    return acc;
}

// One 512-thread block per (8 words, batch); b fast axis. Each thread loads
// exactly one id + one mask element; 9 cut points c[j] = #(id < wbase+j) are
// reduced via REDUX into 4 packed ints; then 8 x 64-thread groups pool their
// words concurrently with the proven ladder.
__global__ void __launch_bounds__(NTHREADS, 4)
fused_kernel(const float* __restrict__ cf,
             const int* __restrict__ word_ids,
             const int* __restrict__ amask,
             float* __restrict__ out,
             float* __restrict__ mask_out) {
    int lid = blockIdx.x;
    int b = lid & (BATCH - 1);        // fast axis
    int wbase = (lid >> 8) * WPB;     // slow axis: words wbase..wbase+7
    int t = threadIdx.x;              // 0..511

    __shared__ int sred[NWARPS * 4];  // per-warp packed partials
    __shared__ int sq[4];             // combined packed sums
    __shared__ int swordnum;

    // --- metadata: one id + one mask per thread (coalesced 2KB + 2KB) ---
    int id = clampw(__ldg(word_ids + b * LSEQ + t));
    int mv = __ldg(amask + b * LSEQ + t);

    int d = id - wbase;   // id < wbase+j  <=>  d < j
    // pack 0/1 counters into 10-bit fields (block sums <= 512 fit)
    int p0 = (d < 0) | ((d < 1) << 10) | ((d < 2) << 20);
    int p1 = (d < 3) | ((d < 4) << 10) | ((d < 5) << 20);
    int p2 = (d < 6) | ((d < 7) << 10) | ((d < 8) << 20);
    int p3 = mv;

    p0 = __reduce_add_sync(0xffffffffu, p0);
    p1 = __reduce_add_sync(0xffffffffu, p1);
    p2 = __reduce_add_sync(0xffffffffu, p2);
    p3 = __reduce_add_sync(0xffffffffu, p3);

    int warp = t >> 5;
    if ((t & 31) == 0) {
        sred[4 * warp + 0] = p0;
        sred[4 * warp + 1] = p1;
        sred[4 * warp + 2] = p2;
        sred[4 * warp + 3] = p3;
    }
    if (t == NTHREADS - 1) swordnum = id + 1;  // sorted -> last is max
    __syncthreads();

    if (t < 4) {
        int q = 0;
        #pragma unroll
        for (int i = 0; i < NWARPS; ++i) q += sred[4 * i + t];
        sq[t] = q;
    }
    __syncthreads();

    int q0 = sq[0], q1 = sq[1], q2 = sq[2];
    int hi = sq[3] - 1;               // 1 + (sum(mask) - 2)
    int wordnum = swordnum;

    // --- pooling: group g (64 threads) handles word wbase+g ---
    int g  = t >> 6;                  // 0..7
    int gt = t & 63;

    // cut points for this group: s = c[g], e = c[g+1]
    int cut[9];
    cut[0] = q0 & 1023; cut[1] = (q0 >> 10) & 1023; cut[2] = (q0 >> 20) & 1023;
    cut[3] = q1 & 1023; cut[4] = (q1 >> 10) & 1023; cut[5] = (q1 >> 20) & 1023;
    cut[6] = q2 & 1023; cut[7] = (q2 >> 10) & 1023; cut[8] = (q2 >> 20) & 1023;
    int s = cut[g];
    int e = cut[g + 1];

    s = s > 1 ? s : 1;
    e = e < hi ? e : hi;
    int n = e - s;                    // may be <= 0 (empty / padded word)

    const int stride4 = BATCH * DDIM / 4;
    const float4* p = reinterpret_cast<const float4*>(cf)
                    + (long long)s * stride4 + b * (DDIM / 4) + gt;

    float4 acc = pool_body(p, stride4, n);

    float inv = 1.0f / (float)(n > 0 ? n : 1);
    acc.x *= inv; acc.y *= inv; acc.z *= inv; acc.w *= inv;

    int w = wbase + g;
    float4* o = reinterpret_cast<float4*>(out)
              + (long long)(w * BATCH + b) * (DDIM / 4) + gt;
    __stcs(o, acc);

    if (gt == 0 && mask_out != nullptr) {
        __stcs(&mask_out[w * BATCH + b], (w < wordnum) ? 1.0f : 0.0f);
    }
}

extern "C" void kernel_launch(void* const* d_in, const int* in_sizes, int n_in,
                              void* d_out, int out_size) {
    const float* char_feats = (const float*)d_in[0];
    const int*   word_ids   = (const int*)d_in[1];
    const int*   amask      = (const int*)d_in[2];
    float* out = (float*)d_out;

    const int feats_elems = NW * BATCH * DDIM;
    float* mask_out = (out_size > feats_elems) ? (out + feats_elems) : nullptr;

    fused_kernel<<<(NW / WPB) * BATCH, NTHREADS>>>(char_feats, word_ids, amask,
                                                   out, mask_out);
}

// round 13
// speedup vs baseline: 1.1742x; 1.1742x over previous
#include <cuda_runtime.h>
#include <cuda_bf16.h>

// char_feats: [L=512, B=256, D=256] f32 (time-major)
// word_ids:   [B, L] i32 (per-row non-decreasing, dense 0..n-1, < 128)
// attention_mask: [B, L] i32
// out: word_feats [W=128, B, D] f32 (+ masks [W, B] f32 if out_size allows)
#define LSEQ 512
#define NW   128
#define BATCH 256
#define DDIM  256
#define WPB   4            // words per block (one 64-thread group each)
#define NTHREADS (64 * WPB)
#define NWARPS (NTHREADS / 32)

__device__ __forceinline__ int clampw(int v) {
    return v < 0 ? 0 : (v > NW - 1 ? NW - 1 : v);
}

// 4/2/1 ladder; single accumulator; evict-first streaming loads.
__device__ __forceinline__ float4 pool_body(const float4* p, int stride4, int n) {
    float4 acc = make_float4(0.f, 0.f, 0.f, 0.f);
    int rem = n;
    while (rem >= 4) {
        float4 v0 = __ldcs(p);
        float4 v1 = __ldcs(p + stride4);
        float4 v2 = __ldcs(p + 2 * stride4);
        float4 v3 = __ldcs(p + 3 * stride4);
        acc.x += v0.x; acc.y += v0.y; acc.z += v0.z; acc.w += v0.w;
        acc.x += v1.x; acc.y += v1.y; acc.z += v1.z; acc.w += v1.w;
        acc.x += v2.x; acc.y += v2.y; acc.z += v2.z; acc.w += v2.w;
        acc.x += v3.x; acc.y += v3.y; acc.z += v3.z; acc.w += v3.w;
        p += 4 * stride4;
        rem -= 4;
    }
    if (rem >= 2) {
        float4 v0 = __ldcs(p);
        float4 v1 = __ldcs(p + stride4);
        acc.x += v0.x; acc.y += v0.y; acc.z += v0.z; acc.w += v0.w;
        acc.x += v1.x; acc.y += v1.y; acc.z += v1.z; acc.w += v1.w;
        p += 2 * stride4;
        rem -= 2;
    }
    if (rem >= 1) {
        float4 v0 = __ldcs(p);
        acc.x += v0.x; acc.y += v0.y; acc.z += v0.z; acc.w += v0.w;
    }
    return acc;
}

// One 256-thread block per (4 words, batch); b fast axis. Metadata row loaded
// once (int2/thread); 5 cut points c[j] = #(id < wbase+j) reduced via REDUX;
// 4 x 64-thread groups then pool their words concurrently.
__global__ void __launch_bounds__(NTHREADS, 8)
fused_kernel(const float* __restrict__ cf,
             const int* __restrict__ word_ids,
             const int* __restrict__ amask,
             float* __restrict__ out,
             float* __restrict__ mask_out) {
    int lid = blockIdx.x;
    int b = lid & (BATCH - 1);        // fast axis
    int wbase = (lid >> 8) * WPB;     // slow axis: words wbase..wbase+3
    int t = threadIdx.x;              // 0..255

    __shared__ int sred[NWARPS * 2];  // per-warp packed partials (p0, p1)
    __shared__ int sq[2];             // combined packed sums
    __shared__ int swordnum;

    // --- metadata: each thread loads 2 ids + 2 mask (int2, coalesced) ---
    const int2* wp = reinterpret_cast<const int2*>(word_ids + b * LSEQ);
    int2 wv = __ldg(wp + t);
    const int2* mp = reinterpret_cast<const int2*>(amask + b * LSEQ);
    int2 mv = __ldg(mp + t);

    int i0 = clampw(wv.x), i1 = clampw(wv.y);
    int d0 = i0 - wbase, d1 = i1 - wbase;   // id < wbase+j  <=>  d < j

    // pack counters into 10-bit fields (block sums <= 512 fit)
    int p0 = ((d0 < 0) + (d1 < 0))
           | (((d0 < 1) + (d1 < 1)) << 10)
           | (((d0 < 2) + (d1 < 2)) << 20);
    int p1 = ((d0 < 3) + (d1 < 3))
           | (((d0 < 4) + (d1 < 4)) << 10)
           | ((mv.x + mv.y) << 20);

    p0 = __reduce_add_sync(0xffffffffu, p0);
    p1 = __reduce_add_sync(0xffffffffu, p1);

    int warp = t >> 5;
    if ((t & 31) == 0) { sred[warp] = p0; sred[NWARPS + warp] = p1; }
    if (t == NTHREADS - 1) swordnum = i1 + 1;  // sorted -> last is max
    __syncthreads();

    if (t < 2) {
        int q = 0;
        #pragma unroll
        for (int i = 0; i < NWARPS; ++i) q += sred[t * NWARPS + i];
        sq[t] = q;
    }
    __syncthreads();

    int q0 = sq[0], q1 = sq[1];
    int hi = (q1 >> 20) - 1;          // 1 + (sum(mask) - 2)
    int wordnum = swordnum;

    // --- pooling: group g (64 threads) handles word wbase+g ---
    int g  = t >> 6;                  // 0..3
    int gt = t & 63;

    int cut[5];
    cut[0] = q0 & 1023; cut[1] = (q0 >> 10) & 1023; cut[2] = (q0 >> 20) & 1023;
    cut[3] = q1 & 1023; cut[4] = (q1 >> 10) & 1023;
    int s = cut[g];
    int e = cut[g + 1];

    s = s > 1 ? s : 1;
    e = e < hi ? e : hi;
    int n = e - s;                    // may be <= 0 (empty / padded word)

    const int stride4 = BATCH * DDIM / 4;
    const float4* p = reinterpret_cast<const float4*>(cf)
                    + (long long)s * stride4 + b * (DDIM / 4) + gt;

    float4 acc = pool_body(p, stride4, n);

    float inv = 1.0f / (float)(n > 0 ? n : 1);
    acc.x *= inv; acc.y *= inv; acc.z *= inv; acc.w *= inv;

    int w = wbase + g;
    float4* o = reinterpret_cast<float4*>(out)
              + (long long)(w * BATCH + b) * (DDIM / 4) + gt;
    __stcs(o, acc);

    if (gt == 0 && mask_out != nullptr) {
        __stcs(&mask_out[w * BATCH + b], (w < wordnum) ? 1.0f : 0.0f);
    }
}

extern "C" void kernel_launch(void* const* d_in, const int* in_sizes, int n_in,
                              void* d_out, int out_size) {
    const float* char_feats = (const float*)d_in[0];
    const int*   word_ids   = (const int*)d_in[1];
    const int*   amask      = (const int*)d_in[2];
    float* out = (float*)d_out;

    const int feats_elems = NW * BATCH * DDIM;
    float* mask_out = (out_size > feats_elems) ? (out + feats_elems) : nullptr;

    fused_kernel<<<(NW / WPB) * BATCH, NTHREADS>>>(char_feats, word_ids, amask,
                                                   out, mask_out);
}